// round 15
// baseline (speedup 1.0000x reference)
#include <cuda_runtime.h>

#define NTIME 1024
#define NB    65536
#define TPB   128   // 4 warps/block; 32 batches per warp (lane-pair x 2 batches ILP)

__device__ __forceinline__ float sel3(float x0, float x1, float x2, int i)
{
    const float a = (i & 1) ? x1 : x0;
    return (i & 2) ? x2 : a;
}

__global__ void __launch_bounds__(TPB)
bts_interp_kernel(const float* __restrict__ times,
                  const float* __restrict__ values,
                  const float* __restrict__ tq,
                  float* __restrict__ out)
{
    const unsigned FULL = 0xFFFFFFFFu;
    const int lane = threadIdx.x & 31;
    const int warp = threadIdx.x >> 5;
    const int half = lane >> 4;                       // 0 = lower pair half
    // Warp covers 32 batches: pair (L, L+16) handles bA = base and bB = base+16.
    const int base = blockIdx.x * 128 + warp * 32 + (lane & 15);
    const int bA = base;
    const int bB = base + 16;

    const float tA = __ldg(&tq[bA]);
    const float tB = __ldg(&tq[bB]);
    const float* colA = times + bA;
    const float* colB = times + bB;

    // ── Coarse (split 2-way per batch, dual-chain interleaved):
    // 64 rows 15,31,...,1023; half h scans coarse idx h*32..h*32+31.
    int   mA = 0, mB = 0;
    float loA = 0.0f, hiA = 0.0f, loB = 0.0f, hiB = 0.0f;
#pragma unroll
    for (int chunk = 0; chunk < 4; ++chunk) {
        float xA[8], xB[8];
#pragma unroll
        for (int i = 0; i < 8; ++i) {
            const int j = half * 32 + chunk * 8 + i;          // coarse index 0..63
            const size_t off = (size_t)(16 * j + 15) * NB;
            xA[i] = __ldg(colA + off);
            xB[i] = __ldg(colB + off);
        }
#pragma unroll
        for (int i = 0; i < 8; ++i) {
            const int jl = chunk * 8 + i;                     // local 0..31
            if (xA[i] <= tA) { loA = xA[i]; mA++; } else if (jl == mA) hiA = xA[i];
            if (xB[i] <= tB) { loB = xB[i]; mB++; } else if (jl == mB) hiB = xB[i];
        }
    }

    // ── Merge pair halves for both batches (sorted segments). ──
    {
        const int   mo  = __shfl_xor_sync(FULL, mA,  16);
        const float loo = __shfl_xor_sync(FULL, loA, 16);
        const float hio = __shfl_xor_sync(FULL, hiA, 16);
        const int   m0 = half ? mo  : mA;
        const int   m1 = half ? mA  : mo;
        const float l0 = half ? loo : loA;
        const float l1 = half ? loA : loo;
        const float h0 = half ? hio : hiA;
        const float h1 = half ? hiA : hio;
        mA  = m0 + m1;
        loA = (m1 > 0)  ? l1 : l0;      // = times[16m-1]
        hiA = (m0 < 32) ? h0 : h1;      // = times[16m+15]
    }
    {
        const int   mo  = __shfl_xor_sync(FULL, mB,  16);
        const float loo = __shfl_xor_sync(FULL, loB, 16);
        const float hio = __shfl_xor_sync(FULL, hiB, 16);
        const int   m0 = half ? mo  : mB;
        const int   m1 = half ? mB  : mo;
        const float l0 = half ? loo : loB;
        const float l1 = half ? loB : loo;
        const float h0 = half ? hio : hiB;
        const float h1 = half ? hiB : hio;
        mB  = m0 + m1;
        loB = (m1 > 0)  ? l1 : l0;
        hiB = (m0 < 32) ? h0 : h1;
    }

    int cA = mA << 4, cB = mB << 4;     // counts in [c, c+15]
    const bool hwA = (mA == 64), hwB = (mB == 64);

    // ── Round 2 (split 2/1, both chains in flight): probe rows c+3, c+7, c+11.
    {
        int a0 = cA + 3, a1 = cA + 7, a2 = cA + 11;
        int b0 = cB + 3, b1 = cB + 7, b2 = cB + 11;
        if (hwA) a0 = a1 = a2 = NTIME - 1;               // in-bounds; discarded
        if (hwB) b0 = b1 = b2 = NTIME - 1;
        float pAa, pAb = 0.0f, pBa, pBb = 0.0f;
        if (half == 0) {
            pAa = __ldg(colA + (size_t)a0 * NB);
            pBa = __ldg(colB + (size_t)b0 * NB);
            pAb = __ldg(colA + (size_t)a2 * NB);
            pBb = __ldg(colB + (size_t)b2 * NB);
        } else {
            pAa = __ldg(colA + (size_t)a1 * NB);
            pBa = __ldg(colB + (size_t)b1 * NB);
        }
        const float eAa = __shfl_xor_sync(FULL, pAa, 16);
        const float eAb = __shfl_xor_sync(FULL, pAb, 16);
        const float eBa = __shfl_xor_sync(FULL, pBa, 16);
        const float eBb = __shfl_xor_sync(FULL, pBb, 16);
        {
            const float p0 = half ? eAa : pAa;
            const float p1 = half ? pAa : eAa;
            const float p2 = half ? eAb : pAb;
            const int s = ((p0 <= tA) ? 1 : 0) + ((p1 <= tA) ? 1 : 0) + ((p2 <= tA) ? 1 : 0);
            if (s > 0) loA = sel3(p0, p1, p2, s - 1);
            if (s < 3) hiA = sel3(p0, p1, p2, s);
            cA += 4 * s;
        }
        {
            const float p0 = half ? eBa : pBa;
            const float p1 = half ? pBa : eBa;
            const float p2 = half ? eBb : pBb;
            const int s = ((p0 <= tB) ? 1 : 0) + ((p1 <= tB) ? 1 : 0) + ((p2 <= tB) ? 1 : 0);
            if (s > 0) loB = sel3(p0, p1, p2, s - 1);
            if (s < 3) hiB = sel3(p0, p1, p2, s);
            cB += 4 * s;
        }
    }

    // ── Round 3 (split 2/1, both chains): probe rows c, c+1, c+2. ──
    {
        int a0 = cA, a1 = cA + 1, a2 = cA + 2;
        int b0 = cB, b1 = cB + 1, b2 = cB + 2;
        if (hwA) a0 = a1 = a2 = NTIME - 1;
        if (hwB) b0 = b1 = b2 = NTIME - 1;
        float qAa, qAb = 0.0f, qBa, qBb = 0.0f;
        if (half == 0) {
            qAa = __ldg(colA + (size_t)a0 * NB);
            qBa = __ldg(colB + (size_t)b0 * NB);
            qAb = __ldg(colA + (size_t)a2 * NB);
            qBb = __ldg(colB + (size_t)b2 * NB);
        } else {
            qAa = __ldg(colA + (size_t)a1 * NB);
            qBa = __ldg(colB + (size_t)b1 * NB);
        }
        const float eAa = __shfl_xor_sync(FULL, qAa, 16);
        const float eAb = __shfl_xor_sync(FULL, qAb, 16);
        const float eBa = __shfl_xor_sync(FULL, qBa, 16);
        const float eBb = __shfl_xor_sync(FULL, qBb, 16);
        {
            const float q0 = half ? eAa : qAa;
            const float q1 = half ? qAa : eAa;
            const float q2 = half ? eAb : qAb;
            const int s = ((q0 <= tA) ? 1 : 0) + ((q1 <= tA) ? 1 : 0) + ((q2 <= tA) ? 1 : 0);
            if (s > 0) loA = sel3(q0, q1, q2, s - 1);  // times[cA-1] exact
            if (s < 3) hiA = sel3(q0, q1, q2, s);      // times[cA]   exact
            cA += s;
        }
        {
            const float q0 = half ? eBa : qBa;
            const float q1 = half ? qBa : eBa;
            const float q2 = half ? eBb : qBb;
            const int s = ((q0 <= tB) ? 1 : 0) + ((q1 <= tB) ? 1 : 0) + ((q2 <= tB) ? 1 : 0);
            if (s > 0) loB = sel3(q0, q1, q2, s - 1);
            if (s < 3) hiB = sel3(q0, q1, q2, s);
            cB += s;
        }
    }

    // ── Values (split 1/1, both chains): rows c-1 / c, clamped. ──
    int iaA = cA - 1; if (iaA < 0) iaA = 0; if (iaA > NTIME - 1) iaA = NTIME - 1;
    int ibA = cA;     if (ibA > NTIME - 1) ibA = NTIME - 1;
    int iaB = cB - 1; if (iaB < 0) iaB = 0; if (iaB > NTIME - 1) iaB = NTIME - 1;
    int ibB = cB;     if (ibB > NTIME - 1) ibB = NTIME - 1;

    float vmA, vmB;
    if (half == 0) {
        vmA = __ldg(&values[(size_t)iaA * NB + bA]);
        vmB = __ldg(&values[(size_t)iaB * NB + bB]);
    } else {
        vmA = __ldg(&values[(size_t)ibA * NB + bA]);
        vmB = __ldg(&values[(size_t)ibB * NB + bB]);
    }
    const float voA = __shfl_xor_sync(FULL, vmA, 16);
    const float voB = __shfl_xor_sync(FULL, vmB, 16);

    if (half == 0) {
        // Batch A
        {
            const bool wrap = hwA || (cA == 0);
            float result;
            if (!wrap) {
                const float s0 = (voA - vmA) / (hiA - loA);
                result = vmA + s0 * (tA - loA);
            } else {
                const float tp = __ldg(&times [(size_t)(NTIME - 2) * NB + bA]);
                const float tl = __ldg(&times [(size_t)(NTIME - 1) * NB + bA]);
                const float vp = __ldg(&values[(size_t)(NTIME - 2) * NB + bA]);
                const float vl = __ldg(&values[(size_t)(NTIME - 1) * NB + bA]);
                const float s0 = (vl - vp) / (tl - tp);
                result = vl + s0 * (tA - tl);
            }
            out[bA] = result;
        }
        // Batch B
        {
            const bool wrap = hwB || (cB == 0);
            float result;
            if (!wrap) {
                const float s0 = (voB - vmB) / (hiB - loB);
                result = vmB + s0 * (tB - loB);
            } else {
                const float tp = __ldg(&times [(size_t)(NTIME - 2) * NB + bB]);
                const float tl = __ldg(&times [(size_t)(NTIME - 1) * NB + bB]);
                const float vp = __ldg(&values[(size_t)(NTIME - 2) * NB + bB]);
                const float vl = __ldg(&values[(size_t)(NTIME - 1) * NB + bB]);
                const float s0 = (vl - vp) / (tl - tp);
                result = vl + s0 * (tB - tl);
            }
            out[bB] = result;
        }
    }
}

extern "C" void kernel_launch(void* const* d_in, const int* in_sizes, int n_in,
                              void* d_out, int out_size)
{
    const float* times  = (const float*)d_in[0];
    const float* values = (const float*)d_in[1];
    const float* tq     = (const float*)d_in[2];
    float* out = (float*)d_out;

    // 2 lanes x 2 batches per lane-pair: 65536 threads, 512 blocks of 128.
    bts_interp_kernel<<<NB / (TPB / 2) / 2 * 1, TPB>>>(times, values, tq, out);
}

// round 16
// speedup vs baseline: 1.1458x; 1.1458x over previous
#include <cuda_runtime.h>

#define NTIME 1024
#define NB    65536
#define TPB   128   // 4 warps/block; 16 batches per warp (2 lanes per batch)

__device__ __forceinline__ float sel3(float x0, float x1, float x2, int i)
{
    const float a = (i & 1) ? x1 : x0;
    return (i & 2) ? x2 : a;
}

__global__ void __launch_bounds__(TPB)
bts_interp_kernel(const float* __restrict__ times,
                  const float* __restrict__ values,
                  const float* __restrict__ tq,
                  float* __restrict__ out)
{
    const unsigned FULL = 0xFFFFFFFFu;
    const int lane = threadIdx.x & 31;
    const int warp = threadIdx.x >> 5;
    const int half = lane >> 4;                       // 0 = lower pair half
    const int b    = blockIdx.x * 64 + warp * 16 + (lane & 15);

    const float t = __ldg(&tq[b]);
    const float* col = times + b;

    // ── Coarse (split 2-way, coalesced): 64 rows 15,31,...,1023.
    // Half h scans coarse indices h*32 .. h*32+31 (a sorted segment).
    int   m_h  = 0;
    float lo_h = 0.0f, hi_h = 0.0f;
#pragma unroll
    for (int chunk = 0; chunk < 4; ++chunk) {
        float x[8];
#pragma unroll
        for (int i = 0; i < 8; ++i) {
            const int j = half * 32 + chunk * 8 + i;          // coarse index 0..63
            x[i] = __ldg(col + (size_t)(16 * j + 15) * NB);
        }
#pragma unroll
        for (int i = 0; i < 8; ++i) {
            const int jl = chunk * 8 + i;                     // local 0..31
            if (x[i] <= t) { lo_h = x[i]; m_h++; }
            else if (jl == m_h) hi_h = x[i];                  // first local failure
        }
    }

    // One-time merge (the only shuffles in the kernel; off the fine chain).
    const int   m_o  = __shfl_xor_sync(FULL, m_h,  16);
    const float lo_o = __shfl_xor_sync(FULL, lo_h, 16);
    const float hi_o = __shfl_xor_sync(FULL, hi_h, 16);
    const int   m0 = half ? m_o  : m_h;
    const int   m1 = half ? m_h  : m_o;
    const float lo0 = half ? lo_o : lo_h;
    const float lo1 = half ? lo_h : lo_o;
    const float hi0 = half ? hi_o : hi_h;
    const float hi1 = half ? hi_h : hi_o;

    const int m = m0 + m1;                  // identical in both halves
    float lo = (m1 > 0)  ? lo1 : lo0;       // = times[16m-1]  (valid iff m > 0)
    float hi = (m0 < 32) ? hi0 : hi1;       // = times[16m+15] (valid iff m < 64)

    int c = m << 4;                         // count in [c, c+15]
    const bool hiwrap = (m == 64);          // count == 1024

    // ── Fine rounds: REDUNDANT across pair-halves (identical addresses ->
    // warp-LDG dedups lanes L/L+16 to one line: 3 x 16 = 48 lines/round, the
    // same wavefront cost as the split version, but NO shuffles / predication
    // in the dependent chain).

    // Round 2: probe rows c+3, c+7, c+11 (counts c+4, c+8, c+12).
    {
        int r0 = c + 3, r1 = c + 7, r2 = c + 11;
        if (hiwrap) { r0 = r1 = r2 = NTIME - 1; }   // in-bounds; result discarded
        const float p0 = __ldg(col + (size_t)r0 * NB);
        const float p1 = __ldg(col + (size_t)r1 * NB);
        const float p2 = __ldg(col + (size_t)r2 * NB);
        const int s = ((p0 <= t) ? 1 : 0) + ((p1 <= t) ? 1 : 0) + ((p2 <= t) ? 1 : 0);
        if (s > 0) lo = sel3(p0, p1, p2, s - 1);
        if (s < 3) hi = sel3(p0, p1, p2, s);
        c += 4 * s;                         // count in [c, c+3]
    }

    // Round 3: probe rows c, c+1, c+2 (counts c+1, c+2, c+3).
    {
        int r0 = c, r1 = c + 1, r2 = c + 2;
        if (hiwrap) { r0 = r1 = r2 = NTIME - 1; }
        const float q0 = __ldg(col + (size_t)r0 * NB);
        const float q1 = __ldg(col + (size_t)r1 * NB);
        const float q2 = __ldg(col + (size_t)r2 * NB);
        const int s2 = ((q0 <= t) ? 1 : 0) + ((q1 <= t) ? 1 : 0) + ((q2 <= t) ? 1 : 0);
        if (s2 > 0) lo = sel3(q0, q1, q2, s2 - 1);  // times[c-1] exact
        if (s2 < 3) hi = sel3(q0, q1, q2, s2);      // times[c]   exact
        c += s2;                                    // exact count (when !hiwrap)
    }

    // ── Values: both halves load both rows (dedup'd: 2 x 16 = 32 lines, same
    // as the split version's single 32-line load), clamped for wrap lanes.
    int ia = c - 1;
    if (ia < 0)         ia = 0;
    if (ia > NTIME - 1) ia = NTIME - 1;
    int ib = c;
    if (ib > NTIME - 1) ib = NTIME - 1;

    const float va = __ldg(&values[(size_t)ia * NB + b]);
    const float vb = __ldg(&values[(size_t)ib * NB + b]);

    if (half == 0) {
        const bool wrap = hiwrap || (c == 0);       // count == 1024 or 0
        float result;
        if (!wrap) {
            const float s0 = (vb - va) / (hi - lo); // bit-exact bracket knots
            result = va + s0 * (t - lo);
        } else {
            // Reference wrap: iv = 1023, isl = 1022.
            const float tp = __ldg(&times [(size_t)(NTIME - 2) * NB + b]);
            const float tl = __ldg(&times [(size_t)(NTIME - 1) * NB + b]);
            const float vp = __ldg(&values[(size_t)(NTIME - 2) * NB + b]);
            const float vl = __ldg(&values[(size_t)(NTIME - 1) * NB + b]);
            const float s0 = (vl - vp) / (tl - tp);
            result = vl + s0 * (t - tl);
        }
        out[b] = result;
    }
}

extern "C" void kernel_launch(void* const* d_in, const int* in_sizes, int n_in,
                              void* d_out, int out_size)
{
    const float* times  = (const float*)d_in[0];
    const float* values = (const float*)d_in[1];
    const float* tq     = (const float*)d_in[2];
    float* out = (float*)d_out;

    // 2 threads per batch: 131072 threads, 1024 blocks of 128.
    bts_interp_kernel<<<(NB * 2) / TPB, TPB>>>(times, values, tq, out);
}